// round 7
// baseline (speedup 1.0000x reference)
#include <cuda_runtime.h>
#include <cuda_fp16.h>

#define NN 50000
#define NE 800000
#define NG 256
#define NF 128
#define SCAN_BLK 1024
#define SCAN_NBLK 49   // 49*1024 = 50176 >= NN+1

typedef unsigned long long u64;

// ---------------- device scratch (no allocation allowed) ----------------
__device__ __half d_hT[NN * NF];
__device__ __half d_hX[NN * NF];
__device__ __half d_Wh[3 * NF * NF];
__device__ float  d_dinv[NN];
__device__ int    d_cnt[NN];
__device__ int    d_off[NN + 1];
__device__ int    d_cursor[NN];
__device__ int2   d_csr[NE];
__device__ u64    d_agg[64];         // packed {flag<<32 | aggregate}
__device__ int    d_is64;
__device__ int    d_gstart[NG + 1];
__device__ float  d_mlpo[NG * 64];

__device__ __forceinline__ uint2 pack4h(float4 v) {
    __half2 a = __floats2half2_rn(v.x, v.y);
    __half2 b = __floats2half2_rn(v.z, v.w);
    uint2 r;
    r.x = *(unsigned*)&a;
    r.y = *(unsigned*)&b;
    return r;
}
__device__ __forceinline__ float4 unpack4h(uint2 u) {
    __half2 a = *(__half2*)&u.x;
    __half2 b = *(__half2*)&u.y;
    float2 f0 = __half22float2(a);
    float2 f1 = __half22float2(b);
    return make_float4(f0.x, f0.y, f1.x, f1.y);
}

__device__ __forceinline__ int ldidx(const void* p, long long i) {
    if (d_is64) return (int)((const long long*)p)[i];
    return ((const int*)p)[i];
}

// ---------------- prep ----------------
__global__ void k_init(const void* edge) {
    int i = blockIdx.x * blockDim.x + threadIdx.x;
    if (i == 0) {
        const int* p = (const int*)edge;
        int any = 0;
        for (int j = 0; j < 64; j++) any |= p[2 * j + 1];
        d_is64 = (any == 0) ? 1 : 0;
    }
    if (i < NN) d_cnt[i] = 0;
    if (i < 64) d_agg[i] = 0ull;
}

__global__ void k_hist(const void* edge) {
    int e = blockIdx.x * blockDim.x + threadIdx.x;
    if (e >= NE) return;
    int c = ldidx(edge, (long long)NE + e);
    atomicAdd(&d_cnt[c], 1);
}

// single-pass scan with aggregate lookback + dinv + cursor
__global__ void k_scan() {
    __shared__ int sm[2][SCAN_BLK];
    __shared__ int pb[64];
    int t = threadIdx.x;
    int bid = blockIdx.x;
    int idx = bid * SCAN_BLK + t;
    int v = (idx < NN) ? d_cnt[idx] : 0;
    sm[0][t] = v;
    __syncthreads();
    int cur = 0;
    for (int d = 1; d < SCAN_BLK; d <<= 1) {
        int add = (t >= d) ? sm[cur][t - d] : 0;
        sm[cur ^ 1][t] = sm[cur][t] + add;
        cur ^= 1;
        __syncthreads();
    }
    int incl = sm[cur][t];
    // publish this block's aggregate (no waiting)
    if (t == SCAN_BLK - 1)
        atomicExch(&d_agg[bid], (1ull << 32) | (unsigned)incl);
    // lookback: spin for all predecessors' aggregates
    if (t < 64) {
        int val = 0;
        if (t < bid) {
            u64 w;
            do { w = atomicAdd(&d_agg[t], 0ull); } while ((w >> 32) == 0ull);
            val = (int)(unsigned)w;
        }
        pb[t] = val;
    }
    __syncthreads();
    if (t < 32) pb[t] += pb[t + 32];
    __syncthreads();
    if (t < 16) pb[t] += pb[t + 16];
    __syncthreads();
    if (t < 8) pb[t] += pb[t + 8];
    __syncthreads();
    if (t < 4) pb[t] += pb[t + 4];
    __syncthreads();
    int base = pb[0] + pb[1] + pb[2] + pb[3];
    int excl = base + incl - v;
    if (idx <= NN) d_off[idx] = excl;
    if (idx < NN) {
        d_dinv[idx] = rsqrtf((float)v + 1.0f);
        d_cursor[idx] = excl;
    }
}

__global__ void k_fill(const void* edge) {
    int e = blockIdx.x * blockDim.x + threadIdx.x;
    if (e >= NE) return;
    int r = ldidx(edge, e);
    int c = ldidx(edge, (long long)NE + e);
    int p = atomicAdd(&d_cursor[c], 1);
    d_csr[p] = make_int2(r, __float_as_int(d_dinv[r] * d_dinv[c]));
}

__global__ void k_wconv(const float* __restrict__ W) {
    int i = blockIdx.x * blockDim.x + threadIdx.x;
    if (i < 3 * NF * NF) d_Wh[i] = __float2half(W[i]);
}

__global__ void k_bounds(const void* batch) {
    int i = blockIdx.x * blockDim.x + threadIdx.x;
    if (i >= NN) return;
    int b = ldidx(batch, i);
    int prev = (i == 0) ? -1 : ldidx(batch, i - 1);
    for (int g = prev + 1; g <= b; g++) d_gstart[g] = i;
    if (i == NN - 1) {
        for (int g = b + 1; g <= NG; g++) d_gstart[g] = NN;
    }
}

// ---------------- shared agg helper: one node -> float4 (per lane) ----------------
__device__ __forceinline__ float4 agg_node(const uint2* __restrict__ base,
                                           const float4* __restrict__ bias4,
                                           int node, int lane)
{
    float di = d_dinv[node];
    float sc = di * di;
    float4 h4 = unpack4h(__ldg(base + (size_t)node * 32 + lane));
    float4 a0 = make_float4(sc * h4.x, sc * h4.y, sc * h4.z, sc * h4.w);
    float4 a1 = make_float4(0.f, 0.f, 0.f, 0.f);
    float4 a2 = a1, a3 = a1;

    int p = d_off[node], e = d_off[node + 1];
    for (; p + 8 <= e; p += 8) {
        int2 cc[8];
        uint2 vv[8];
#pragma unroll
        for (int q = 0; q < 8; q++) cc[q] = __ldg(&d_csr[p + q]);
#pragma unroll
        for (int q = 0; q < 8; q++) vv[q] = __ldg(base + (size_t)cc[q].x * 32 + lane);
#pragma unroll
        for (int q = 0; q < 8; q++) {
            float w = __int_as_float(cc[q].y);
            float4 v = unpack4h(vv[q]);
            float4* a = (q & 3) == 0 ? &a0 : (q & 3) == 1 ? &a1 : (q & 3) == 2 ? &a2 : &a3;
            a->x = fmaf(w, v.x, a->x); a->y = fmaf(w, v.y, a->y);
            a->z = fmaf(w, v.z, a->z); a->w = fmaf(w, v.w, a->w);
        }
    }
    for (; p < e; p++) {
        int2 c = __ldg(&d_csr[p]);
        float4 v = unpack4h(__ldg(base + (size_t)c.x * 32 + lane));
        float w = __int_as_float(c.y);
        a0.x = fmaf(w, v.x, a0.x); a0.y = fmaf(w, v.y, a0.y);
        a0.z = fmaf(w, v.z, a0.z); a0.w = fmaf(w, v.w, a0.w);
    }
    float4 b4 = __ldg(bias4 + lane);
    float4 rv;
    rv.x = fmaxf(a0.x + a1.x + a2.x + a3.x + b4.x, 0.f);
    rv.y = fmaxf(a0.y + a1.y + a2.y + a3.y + b4.y, 0.f);
    rv.z = fmaxf(a0.z + a1.z + a2.z + a3.z + b4.z, 0.f);
    rv.w = fmaxf(a0.w + a1.w + a2.w + a3.w + b4.w, 0.f);
    return rv;
}

#define SM_STRIDE 136   // halves; conflict-free mma fragment loads

// ---------------- HMMA core on smem tiles ----------------
__device__ __forceinline__ void mma_phase(const __half* Asm, const __half* Bsm,
                                          __half* C, int row0, int nrows, int tid)
{
    int lane = tid & 31, wid = tid >> 5;
    int wm = (wid & 3) * 32;
    int wn = (wid >> 2) * 64;
    int r = lane >> 2;
    int c2 = (lane & 3) * 2;

    float acc[2][8][4];
#pragma unroll
    for (int mt = 0; mt < 2; mt++)
#pragma unroll
        for (int nt = 0; nt < 8; nt++)
#pragma unroll
            for (int q = 0; q < 4; q++) acc[mt][nt][q] = 0.f;

#pragma unroll
    for (int ks = 0; ks < 8; ks++) {
        int kb = ks * 16;
        unsigned af[2][4];
#pragma unroll
        for (int mt = 0; mt < 2; mt++) {
            int rowb = wm + mt * 16;
            af[mt][0] = *(unsigned*)&Asm[(rowb + r) * SM_STRIDE + kb + c2];
            af[mt][1] = *(unsigned*)&Asm[(rowb + r + 8) * SM_STRIDE + kb + c2];
            af[mt][2] = *(unsigned*)&Asm[(rowb + r) * SM_STRIDE + kb + c2 + 8];
            af[mt][3] = *(unsigned*)&Asm[(rowb + r + 8) * SM_STRIDE + kb + c2 + 8];
        }
        unsigned bf[8][2];
#pragma unroll
        for (int nt = 0; nt < 8; nt++) {
            int n = wn + nt * 8 + r;
            bf[nt][0] = *(unsigned*)&Bsm[n * SM_STRIDE + kb + c2];
            bf[nt][1] = *(unsigned*)&Bsm[n * SM_STRIDE + kb + c2 + 8];
        }
#pragma unroll
        for (int mt = 0; mt < 2; mt++)
#pragma unroll
            for (int nt = 0; nt < 8; nt++) {
                asm volatile(
                    "mma.sync.aligned.m16n8k16.row.col.f32.f16.f16.f32 "
                    "{%0,%1,%2,%3}, {%4,%5,%6,%7}, {%8,%9}, {%0,%1,%2,%3};"
                    : "+f"(acc[mt][nt][0]), "+f"(acc[mt][nt][1]),
                      "+f"(acc[mt][nt][2]), "+f"(acc[mt][nt][3])
                    : "r"(af[mt][0]), "r"(af[mt][1]), "r"(af[mt][2]), "r"(af[mt][3]),
                      "r"(bf[nt][0]), "r"(bf[nt][1]));
            }
    }

#pragma unroll
    for (int mt = 0; mt < 2; mt++) {
        int gr0 = row0 + wm + mt * 16 + r;
        int gr1 = gr0 + 8;
#pragma unroll
        for (int nt = 0; nt < 8; nt++) {
            int gc = wn + nt * 8 + c2;
            __half2 h0 = __floats2half2_rn(acc[mt][nt][0], acc[mt][nt][1]);
            __half2 h1 = __floats2half2_rn(acc[mt][nt][2], acc[mt][nt][3]);
            if (gr0 < nrows) *(__half2*)(C + (size_t)gr0 * 128 + gc) = h0;
            if (gr1 < nrows) *(__half2*)(C + (size_t)gr1 * 128 + gc) = h1;
        }
    }
}

// ---------------- layer-1 GEMM (fp32 A from gmem) ----------------
__global__ __launch_bounds__(256) void k_gemmT(
    const float* __restrict__ Af, const __half* __restrict__ Wh,
    __half* __restrict__ C, int nrows)
{
    extern __shared__ __half smh[];
    __half* Asm = smh;
    __half* Bsm = smh + 128 * SM_STRIDE;
    int tid = threadIdx.x;
    int row0 = blockIdx.x * 128;

#pragma unroll
    for (int i = 0; i < 16; i++) {
        int idx = tid + i * 256;
        int row = idx >> 5;
        int c4 = (idx & 31) << 2;
        float4 v = make_float4(0.f, 0.f, 0.f, 0.f);
        if (row0 + row < nrows)
            v = *(const float4*)(Af + (size_t)(row0 + row) * 128 + c4);
        *(uint2*)&Asm[row * SM_STRIDE + c4] = pack4h(v);
    }
    {
        const uint4* Wv = (const uint4*)Wh;
#pragma unroll
        for (int i = 0; i < 8; i++) {
            int idx = tid + i * 256;
            int row = idx >> 4;
            int c8 = (idx & 15) << 3;
            *(uint4*)&Bsm[row * SM_STRIDE + c8] = Wv[idx];
        }
    }
    __syncthreads();
    mma_phase(Asm, Bsm, C, row0, nrows, tid);
}

// ---------------- fused agg(layer i) + GEMM(layer i+1) ----------------
__global__ __launch_bounds__(256) void k_aggGemm(
    const __half* __restrict__ ht, const float* __restrict__ bias,
    const __half* __restrict__ Wh, __half* __restrict__ C)
{
    extern __shared__ __half smh[];
    __half* Asm = smh;
    __half* Bsm = smh + 128 * SM_STRIDE;
    int tid = threadIdx.x;
    int row0 = blockIdx.x * 128;
    int lane = tid & 31, wid = tid >> 5;

    // W tile load
    {
        const uint4* Wv = (const uint4*)Wh;
#pragma unroll
        for (int i = 0; i < 8; i++) {
            int idx = tid + i * 256;
            int row = idx >> 4;
            int c8 = (idx & 15) << 3;
            *(uint4*)&Bsm[row * SM_STRIDE + c8] = Wv[idx];
        }
    }

    // aggregation phase: warp handles 16 nodes, results -> Asm
    const uint2* base = (const uint2*)ht;
    const float4* bias4 = (const float4*)bias;
#pragma unroll 1
    for (int i = 0; i < 16; i++) {
        int nl = wid * 16 + i;
        int node = row0 + nl;
        uint2 packed = make_uint2(0u, 0u);
        if (node < NN) packed = pack4h(agg_node(base, bias4, node, lane));
        *(uint2*)&Asm[nl * SM_STRIDE + lane * 4] = packed;
    }
    __syncthreads();

    mma_phase(Asm, Bsm, C, row0, NN, tid);
}

// ---------------- final agg (writes fp16 node features for pooling) ----------------
__global__ __launch_bounds__(256) void k_agg(const __half* __restrict__ ht,
                                             const float* __restrict__ bias,
                                             __half* __restrict__ out)
{
    int node = (int)((blockIdx.x * (unsigned)blockDim.x + threadIdx.x) >> 5);
    if (node >= NN) return;
    int lane = threadIdx.x & 31;
    float4 rv = agg_node((const uint2*)ht, (const float4*)bias, node, lane);
    *(uint2*)(out + (size_t)node * 128 + lane * 4) = pack4h(rv);
}

// ---------------- small dense helpers ----------------
__device__ __forceinline__ float dotN(const float* __restrict__ a,
                                      const float* __restrict__ w, int n) {
    float s0 = 0.f, s1 = 0.f, s2 = 0.f, s3 = 0.f;
    for (int k = 0; k < n; k += 4) {
        float4 wv = __ldg((const float4*)(w + k));
        s0 = fmaf(a[k + 0], wv.x, s0);
        s1 = fmaf(a[k + 1], wv.y, s1);
        s2 = fmaf(a[k + 2], wv.z, s2);
        s3 = fmaf(a[k + 3], wv.w, s3);
    }
    return (s0 + s1) + (s2 + s3);
}

__global__ __launch_bounds__(256) void k_mlp(
    const float* __restrict__ mol,
    const float* __restrict__ mW, const float* __restrict__ mB,
    const float* __restrict__ moW, const float* __restrict__ moB)
{
    __shared__ float a[256], b[256];
    int g = blockIdx.x, t = threadIdx.x;
    a[t] = mol[g * 256 + t];
    __syncthreads();
    b[t] = fmaxf(dotN(a, mW + t * 256, 256) + mB[t], 0.f);
    __syncthreads();
    a[t] = fmaxf(dotN(b, mW + 65536 + t * 256, 256) + mB[256 + t], 0.f);
    __syncthreads();
    if (t < 64) d_mlpo[g * 64 + t] = fmaxf(dotN(a, moW + t * 256, 256) + moB[t], 0.f);
}

__global__ __launch_bounds__(256) void k_heads2(
    const __half* __restrict__ hnode,
    const float* __restrict__ goW, const float* __restrict__ goB,
    const float* __restrict__ p1W, const float* __restrict__ p1B,
    const float* __restrict__ p2W, const float* __restrict__ p2B,
    const float* __restrict__ oW, const float* __restrict__ oB,
    float* __restrict__ out)
{
    __shared__ float cat[192], pooled[128], red[256], b[256], a[256];
    int g = blockIdx.x, t = threadIdx.x;

    int s = d_gstart[g], e = d_gstart[g + 1];
    float acc = 0.f;
    int f = t & 127, half = t >> 7;
    for (int n = s + half; n < e; n += 2)
        acc += __half2float(hnode[(size_t)n * 128 + f]);
    red[t] = acc;
    if (t < 64) cat[128 + t] = d_mlpo[g * 64 + t];
    __syncthreads();
    if (t < 128) pooled[t] = (red[t] + red[t + 128]) / (float)max(e - s, 1);
    __syncthreads();
    if (t < 128) cat[t] = dotN(pooled, goW + t * 128, 128) + goB[t];
    __syncthreads();

    b[t] = fmaxf(dotN(cat, p1W + t * 192, 192) + p1B[t], 0.f);
    __syncthreads();
    a[t] = fmaxf(dotN(b, p2W + t * 256, 256) + p2B[t], 0.f);
    __syncthreads();
    red[t] = a[t] * oW[t];
    __syncthreads();
    for (int d = 128; d > 0; d >>= 1) {
        if (t < d) red[t] += red[t + d];
        __syncthreads();
    }
    if (t == 0) out[g] = red[0] + oB[0];
}

// ---------------- host ----------------
#define GEMM_SMEM (2 * 128 * SM_STRIDE * (int)sizeof(__half))

struct HxCtx {
    cudaStream_t s1, s2;
    cudaEvent_t ev0, ev1, ev2, ev3;
    HxCtx() {
        cudaStreamCreateWithFlags(&s1, cudaStreamNonBlocking);
        cudaStreamCreateWithFlags(&s2, cudaStreamNonBlocking);
        cudaEventCreateWithFlags(&ev0, cudaEventDisableTiming);
        cudaEventCreateWithFlags(&ev1, cudaEventDisableTiming);
        cudaEventCreateWithFlags(&ev2, cudaEventDisableTiming);
        cudaEventCreateWithFlags(&ev3, cudaEventDisableTiming);
        cudaFuncSetAttribute(k_gemmT, cudaFuncAttributeMaxDynamicSharedMemorySize, GEMM_SMEM);
        cudaFuncSetAttribute(k_aggGemm, cudaFuncAttributeMaxDynamicSharedMemorySize, GEMM_SMEM);
    }
};

extern "C" void kernel_launch(void* const* d_in, const int* in_sizes, int n_in,
                              void* d_out, int out_size)
{
    static HxCtx ctx;

    const float* x    = (const float*)d_in[0];
    const void*  ei   = d_in[1];
    const void*  bi   = d_in[2];
    const float* mol  = (const float*)d_in[3];
    const float* gcnW = (const float*)d_in[4];
    const float* gcnB = (const float*)d_in[5];
    const float* goW  = (const float*)d_in[6];
    const float* goB  = (const float*)d_in[7];
    const float* mW   = (const float*)d_in[8];
    const float* mB   = (const float*)d_in[9];
    const float* moW  = (const float*)d_in[10];
    const float* moB  = (const float*)d_in[11];
    const float* p1W  = (const float*)d_in[12];
    const float* p1B  = (const float*)d_in[13];
    const float* p2W  = (const float*)d_in[14];
    const float* p2B  = (const float*)d_in[15];
    const float* oW   = (const float*)d_in[16];
    const float* oB   = (const float*)d_in[17];
    float* out = (float*)d_out;

    void *pT, *pX, *pW;
    cudaGetSymbolAddress(&pT, d_hT);
    cudaGetSymbolAddress(&pX, d_hX);
    cudaGetSymbolAddress(&pW, d_Wh);
    __half* hT = (__half*)pT;
    __half* hX = (__half*)pX;
    __half* Wh = (__half*)pW;

    const int nthr = 256;
    int gN = (NN + nthr - 1) / nthr;
    int gE = (NE + nthr - 1) / nthr;
    int gGemm = (NN + 127) / 128;
    int gAgg = (NN * 32 + nthr - 1) / nthr;

    cudaStream_t L = 0;

    // 1: init (+is64 detect, scan flag reset)
    k_init<<<gN, nthr, 0, L>>>(ei);
    cudaEventRecord(ctx.ev0, L);
    cudaStreamWaitEvent(ctx.s1, ctx.ev0, 0);
    cudaStreamWaitEvent(ctx.s2, ctx.ev0, 0);

    // s1: CSR prep   (2,3,4)
    k_hist<<<gE, nthr, 0, ctx.s1>>>(ei);
    k_scan<<<SCAN_NBLK, SCAN_BLK, 0, ctx.s1>>>();
    k_fill<<<gE, nthr, 0, ctx.s1>>>(ei);
    cudaEventRecord(ctx.ev1, ctx.s1);

    // s2: weight convert (5)
    k_wconv<<<(3 * NF * NF + 255) / 256, 256, 0, ctx.s2>>>(gcnW);
    cudaEventRecord(ctx.ev3, ctx.s2);

    // L: layer-1 GEMM (6) -- ncu -s 5 -c 1 lands here
    cudaStreamWaitEvent(L, ctx.ev3, 0);
    k_gemmT<<<gGemm, 256, GEMM_SMEM, L>>>(x, Wh, hT, NN);

    // s2: bounds + MLP branch (7,8)
    k_bounds<<<gN, nthr, 0, ctx.s2>>>(bi);
    k_mlp<<<NG, nthr, 0, ctx.s2>>>(mol, mW, mB, moW, moB);
    cudaEventRecord(ctx.ev2, ctx.s2);

    // L: fused GCN stack
    cudaStreamWaitEvent(L, ctx.ev1, 0);
    k_aggGemm<<<gGemm, 256, GEMM_SMEM, L>>>(hT, gcnB, Wh + NF * NF, hX);
    k_aggGemm<<<gGemm, 256, GEMM_SMEM, L>>>(hX, gcnB + 128, Wh + 2 * NF * NF, hT);
    k_agg<<<gAgg, 256, 0, L>>>(hT, gcnB + 256, hX);

    cudaStreamWaitEvent(L, ctx.ev2, 0);
    k_heads2<<<NG, 256, 0, L>>>(hX, goW, goB, p1W, p1B, p2W, p2B, oW, oB, out);
}

// round 8
// speedup vs baseline: 1.3490x; 1.3490x over previous
#include <cuda_runtime.h>
#include <cuda_fp16.h>

#define NN 50000
#define NE 800000
#define NG 256
#define NF 128
#define SCAN_BLK 1024
#define SCAN_NBLK 49   // 49*1024 = 50176 >= NN+1

typedef unsigned long long u64;

// ---------------- device scratch (no allocation allowed) ----------------
__device__ __align__(16) __half d_hT[NN * NF];     // dinv-scaled GEMM out
__device__ __align__(16) __half d_hX[NN * NF];     // agg out (raw h1)
__device__ __align__(16) __half d_Wh[3 * NF * NF];
__device__ float  d_dinv[NN];
__device__ int    d_cnt[NN];
__device__ int    d_off[NN + 1];
__device__ int    d_cursor[NN];
__device__ int    d_csrs[NE];        // src only (weights factored out)
__device__ u64    d_agg[64];         // packed {flag<<32 | aggregate}
__device__ int    d_is64;
__device__ int    d_gstart[NG + 1];
__device__ float  d_mlpo[NG * 64];

__device__ __forceinline__ uint2 pack4h(float4 v) {
    __half2 a = __floats2half2_rn(v.x, v.y);
    __half2 b = __floats2half2_rn(v.z, v.w);
    uint2 r;
    r.x = *(unsigned*)&a;
    r.y = *(unsigned*)&b;
    return r;
}
__device__ __forceinline__ float4 unpack4h(uint2 u) {
    __half2 a = *(__half2*)&u.x;
    __half2 b = *(__half2*)&u.y;
    float2 f0 = __half22float2(a);
    float2 f1 = __half22float2(b);
    return make_float4(f0.x, f0.y, f1.x, f1.y);
}

__device__ __forceinline__ int ldidx(const void* p, long long i) {
    if (d_is64) return (int)((const long long*)p)[i];
    return ((const int*)p)[i];
}

// ---------------- prep ----------------
__global__ void k_init(const void* edge) {
    int i = blockIdx.x * blockDim.x + threadIdx.x;
    if (i == 0) {
        const int* p = (const int*)edge;
        int any = 0;
        for (int j = 0; j < 64; j++) any |= p[2 * j + 1];
        d_is64 = (any == 0) ? 1 : 0;
    }
    if (i < NN) d_cnt[i] = 0;
    if (i < 64) d_agg[i] = 0ull;
}

__global__ void k_hist(const void* edge) {
    int e = blockIdx.x * blockDim.x + threadIdx.x;
    if (e >= NE) return;
    int c = ldidx(edge, (long long)NE + e);
    atomicAdd(&d_cnt[c], 1);
}

// single-pass scan (aggregate lookback) + dinv + cursor
__global__ void k_scan() {
    __shared__ int sm[2][SCAN_BLK];
    __shared__ int pb[64];
    int t = threadIdx.x;
    int bid = blockIdx.x;
    int idx = bid * SCAN_BLK + t;
    int v = (idx < NN) ? d_cnt[idx] : 0;
    sm[0][t] = v;
    __syncthreads();
    int cur = 0;
    for (int d = 1; d < SCAN_BLK; d <<= 1) {
        int add = (t >= d) ? sm[cur][t - d] : 0;
        sm[cur ^ 1][t] = sm[cur][t] + add;
        cur ^= 1;
        __syncthreads();
    }
    int incl = sm[cur][t];
    if (t == SCAN_BLK - 1)
        atomicExch(&d_agg[bid], (1ull << 32) | (unsigned)incl);
    if (t < 64) {
        int val = 0;
        if (t < bid) {
            u64 w;
            do { w = atomicAdd(&d_agg[t], 0ull); } while ((w >> 32) == 0ull);
            val = (int)(unsigned)w;
        }
        pb[t] = val;
    }
    __syncthreads();
    if (t < 32) pb[t] += pb[t + 32];
    __syncthreads();
    if (t < 16) pb[t] += pb[t + 16];
    __syncthreads();
    if (t < 8) pb[t] += pb[t + 8];
    __syncthreads();
    if (t < 4) pb[t] += pb[t + 4];
    __syncthreads();
    int base = pb[0] + pb[1] + pb[2] + pb[3];
    int excl = base + incl - v;
    if (idx <= NN) d_off[idx] = excl;
    if (idx < NN) {
        d_dinv[idx] = rsqrtf((float)v + 1.0f);
        d_cursor[idx] = excl;
    }
}

// CSR fill: src index only (no weights — factored into dinv scaling)
__global__ void k_fill(const void* edge) {
    int e = blockIdx.x * blockDim.x + threadIdx.x;
    if (e >= NE) return;
    int r = ldidx(edge, e);
    int c = ldidx(edge, (long long)NE + e);
    int p = atomicAdd(&d_cursor[c], 1);
    d_csrs[p] = r;
}

__global__ void k_wconv(const float* __restrict__ W) {
    int i = blockIdx.x * blockDim.x + threadIdx.x;
    if (i < 3 * NF * NF) d_Wh[i] = __float2half(W[i]);
}

__global__ void k_bounds(const void* batch) {
    int i = blockIdx.x * blockDim.x + threadIdx.x;
    if (i >= NN) return;
    int b = ldidx(batch, i);
    int prev = (i == 0) ? -1 : ldidx(batch, i - 1);
    for (int g = prev + 1; g <= b; g++) d_gstart[g] = i;
    if (i == NN - 1) {
        for (int g = b + 1; g <= NG; g++) d_gstart[g] = NN;
    }
}

#define SM_STRIDE 136   // halves; conflict-free mma fragment loads

// ---------------- HMMA core; epilogue scales row n by dinv[n] ----------------
__device__ __forceinline__ void mma_phase(const __half* Asm, const __half* Bsm,
                                          __half* C, int row0, int nrows, int tid)
{
    int lane = tid & 31, wid = tid >> 5;
    int wm = (wid & 3) * 32;
    int wn = (wid >> 2) * 64;
    int r = lane >> 2;
    int c2 = (lane & 3) * 2;

    float acc[2][8][4];
#pragma unroll
    for (int mt = 0; mt < 2; mt++)
#pragma unroll
        for (int nt = 0; nt < 8; nt++)
#pragma unroll
            for (int q = 0; q < 4; q++) acc[mt][nt][q] = 0.f;

#pragma unroll
    for (int ks = 0; ks < 8; ks++) {
        int kb = ks * 16;
        unsigned af[2][4];
#pragma unroll
        for (int mt = 0; mt < 2; mt++) {
            int rowb = wm + mt * 16;
            af[mt][0] = *(unsigned*)&Asm[(rowb + r) * SM_STRIDE + kb + c2];
            af[mt][1] = *(unsigned*)&Asm[(rowb + r + 8) * SM_STRIDE + kb + c2];
            af[mt][2] = *(unsigned*)&Asm[(rowb + r) * SM_STRIDE + kb + c2 + 8];
            af[mt][3] = *(unsigned*)&Asm[(rowb + r + 8) * SM_STRIDE + kb + c2 + 8];
        }
        unsigned bf[8][2];
#pragma unroll
        for (int nt = 0; nt < 8; nt++) {
            int n = wn + nt * 8 + r;
            bf[nt][0] = *(unsigned*)&Bsm[n * SM_STRIDE + kb + c2];
            bf[nt][1] = *(unsigned*)&Bsm[n * SM_STRIDE + kb + c2 + 8];
        }
#pragma unroll
        for (int mt = 0; mt < 2; mt++)
#pragma unroll
            for (int nt = 0; nt < 8; nt++) {
                asm volatile(
                    "mma.sync.aligned.m16n8k16.row.col.f32.f16.f16.f32 "
                    "{%0,%1,%2,%3}, {%4,%5,%6,%7}, {%8,%9}, {%0,%1,%2,%3};"
                    : "+f"(acc[mt][nt][0]), "+f"(acc[mt][nt][1]),
                      "+f"(acc[mt][nt][2]), "+f"(acc[mt][nt][3])
                    : "r"(af[mt][0]), "r"(af[mt][1]), "r"(af[mt][2]), "r"(af[mt][3]),
                      "r"(bf[nt][0]), "r"(bf[nt][1]));
            }
    }

#pragma unroll
    for (int mt = 0; mt < 2; mt++) {
        int gr0 = row0 + wm + mt * 16 + r;
        int gr1 = gr0 + 8;
        float dv0 = (gr0 < nrows) ? d_dinv[gr0] : 0.f;
        float dv1 = (gr1 < nrows) ? d_dinv[gr1] : 0.f;
#pragma unroll
        for (int nt = 0; nt < 8; nt++) {
            int gc = wn + nt * 8 + c2;
            __half2 h0 = __floats2half2_rn(dv0 * acc[mt][nt][0], dv0 * acc[mt][nt][1]);
            __half2 h1 = __floats2half2_rn(dv1 * acc[mt][nt][2], dv1 * acc[mt][nt][3]);
            if (gr0 < nrows) *(__half2*)(C + (size_t)gr0 * 128 + gc) = h0;
            if (gr1 < nrows) *(__half2*)(C + (size_t)gr1 * 128 + gc) = h1;
        }
    }
}

// GEMM: A fp32 (layer 1) or fp16 (layers 2,3); W fp16; C = dinv-scaled fp16
__global__ __launch_bounds__(256) void k_gemmT(
    const void* __restrict__ Ap, int a_fp32,
    const __half* __restrict__ Wh,
    __half* __restrict__ C, int nrows)
{
    extern __shared__ __half smh[];
    __half* Asm = smh;
    __half* Bsm = smh + 128 * SM_STRIDE;
    int tid = threadIdx.x;
    int row0 = blockIdx.x * 128;

    if (a_fp32) {
        const float* Af = (const float*)Ap;
#pragma unroll
        for (int i = 0; i < 16; i++) {
            int idx = tid + i * 256;
            int row = idx >> 5;
            int c4 = (idx & 31) << 2;
            float4 v = make_float4(0.f, 0.f, 0.f, 0.f);
            if (row0 + row < nrows)
                v = *(const float4*)(Af + (size_t)(row0 + row) * 128 + c4);
            *(uint2*)&Asm[row * SM_STRIDE + c4] = pack4h(v);
        }
    } else {
        const uint4* Ah = (const uint4*)Ap;
#pragma unroll
        for (int i = 0; i < 8; i++) {
            int idx = tid + i * 256;
            int row = idx >> 4;
            int c8 = (idx & 15) << 3;
            uint4 v = make_uint4(0u, 0u, 0u, 0u);
            if (row0 + row < nrows)
                v = Ah[(size_t)(row0 + row) * 16 + (idx & 15)];
            *(uint4*)&Asm[row * SM_STRIDE + c8] = v;
        }
    }
    {
        const uint4* Wv = (const uint4*)Wh;
#pragma unroll
        for (int i = 0; i < 8; i++) {
            int idx = tid + i * 256;
            int row = idx >> 4;
            int c8 = (idx & 15) << 3;
            *(uint4*)&Bsm[row * SM_STRIDE + c8] = Wv[idx];
        }
    }
    __syncthreads();
    mma_phase(Asm, Bsm, C, row0, nrows, tid);
}

// ---------------- agg: pure neighbor sum (weights pre-factored) ----------------
// out[n] = relu(dinv[n] * (ht'[n] + sum_src ht'[src]) + bias)
__global__ __launch_bounds__(256) void k_agg(const __half* __restrict__ ht,
                                             const float* __restrict__ bias,
                                             __half* __restrict__ out)
{
    int node = (int)((blockIdx.x * (unsigned)blockDim.x + threadIdx.x) >> 5);
    if (node >= NN) return;
    int lane = threadIdx.x & 31;
    const uint2* base = (const uint2*)ht;

    float4 a0 = unpack4h(__ldg(base + (size_t)node * 32 + lane));  // self term
    float4 a1 = make_float4(0.f, 0.f, 0.f, 0.f);
    float4 a2 = a1, a3 = a1;

    int p = d_off[node], e = d_off[node + 1];
    for (; p + 8 <= e; p += 8) {
        int ss[8];
        uint2 vv[8];
#pragma unroll
        for (int q = 0; q < 8; q++) ss[q] = __ldg(&d_csrs[p + q]);
#pragma unroll
        for (int q = 0; q < 8; q++) vv[q] = __ldg(base + (size_t)ss[q] * 32 + lane);
#pragma unroll
        for (int q = 0; q < 8; q++) {
            float4 v = unpack4h(vv[q]);
            float4* a = (q & 3) == 0 ? &a0 : (q & 3) == 1 ? &a1 : (q & 3) == 2 ? &a2 : &a3;
            a->x += v.x; a->y += v.y; a->z += v.z; a->w += v.w;
        }
    }
    for (; p < e; p++) {
        int s = __ldg(&d_csrs[p]);
        float4 v = unpack4h(__ldg(base + (size_t)s * 32 + lane));
        a0.x += v.x; a0.y += v.y; a0.z += v.z; a0.w += v.w;
    }
    float dv = d_dinv[node];
    float4 b4 = __ldg((const float4*)bias + lane);
    float4 rv;
    rv.x = fmaxf(fmaf(dv, a0.x + a1.x + a2.x + a3.x, b4.x), 0.f);
    rv.y = fmaxf(fmaf(dv, a0.y + a1.y + a2.y + a3.y, b4.y), 0.f);
    rv.z = fmaxf(fmaf(dv, a0.z + a1.z + a2.z + a3.z, b4.z), 0.f);
    rv.w = fmaxf(fmaf(dv, a0.w + a1.w + a2.w + a3.w, b4.w), 0.f);
    *(uint2*)(out + (size_t)node * 128 + lane * 4) = pack4h(rv);
}

// ---------------- small dense helpers ----------------
__device__ __forceinline__ float dotN(const float* __restrict__ a,
                                      const float* __restrict__ w, int n) {
    float s0 = 0.f, s1 = 0.f, s2 = 0.f, s3 = 0.f;
    for (int k = 0; k < n; k += 4) {
        float4 wv = __ldg((const float4*)(w + k));
        s0 = fmaf(a[k + 0], wv.x, s0);
        s1 = fmaf(a[k + 1], wv.y, s1);
        s2 = fmaf(a[k + 2], wv.z, s2);
        s3 = fmaf(a[k + 3], wv.w, s3);
    }
    return (s0 + s1) + (s2 + s3);
}

__global__ __launch_bounds__(256) void k_mlp(
    const float* __restrict__ mol,
    const float* __restrict__ mW, const float* __restrict__ mB,
    const float* __restrict__ moW, const float* __restrict__ moB)
{
    __shared__ float a[256], b[256];
    int g = blockIdx.x, t = threadIdx.x;
    a[t] = mol[g * 256 + t];
    __syncthreads();
    b[t] = fmaxf(dotN(a, mW + t * 256, 256) + mB[t], 0.f);
    __syncthreads();
    a[t] = fmaxf(dotN(b, mW + 65536 + t * 256, 256) + mB[256 + t], 0.f);
    __syncthreads();
    if (t < 64) d_mlpo[g * 64 + t] = fmaxf(dotN(a, moW + t * 256, 256) + moB[t], 0.f);
}

__global__ __launch_bounds__(256) void k_heads2(
    const __half* __restrict__ hnode,
    const float* __restrict__ goW, const float* __restrict__ goB,
    const float* __restrict__ p1W, const float* __restrict__ p1B,
    const float* __restrict__ p2W, const float* __restrict__ p2B,
    const float* __restrict__ oW, const float* __restrict__ oB,
    float* __restrict__ out)
{
    __shared__ float cat[192], pooled[128], red[256], b[256], a[256];
    int g = blockIdx.x, t = threadIdx.x;

    int s = d_gstart[g], e = d_gstart[g + 1];
    float acc = 0.f;
    int f = t & 127, half = t >> 7;
    for (int n = s + half; n < e; n += 2)
        acc += __half2float(hnode[(size_t)n * 128 + f]);
    red[t] = acc;
    if (t < 64) cat[128 + t] = d_mlpo[g * 64 + t];
    __syncthreads();
    if (t < 128) pooled[t] = (red[t] + red[t + 128]) / (float)max(e - s, 1);
    __syncthreads();
    if (t < 128) cat[t] = dotN(pooled, goW + t * 128, 128) + goB[t];
    __syncthreads();

    b[t] = fmaxf(dotN(cat, p1W + t * 192, 192) + p1B[t], 0.f);
    __syncthreads();
    a[t] = fmaxf(dotN(b, p2W + t * 256, 256) + p2B[t], 0.f);
    __syncthreads();
    red[t] = a[t] * oW[t];
    __syncthreads();
    for (int d = 128; d > 0; d >>= 1) {
        if (t < d) red[t] += red[t + d];
        __syncthreads();
    }
    if (t == 0) out[g] = red[0] + oB[0];
}

// ---------------- host ----------------
#define GEMM_SMEM (2 * 128 * SM_STRIDE * (int)sizeof(__half))

struct HxCtx {
    cudaStream_t s1, s2;
    cudaEvent_t ev0, ev1, ev2, ev3, ev4;
    HxCtx() {
        cudaStreamCreateWithFlags(&s1, cudaStreamNonBlocking);
        cudaStreamCreateWithFlags(&s2, cudaStreamNonBlocking);
        cudaEventCreateWithFlags(&ev0, cudaEventDisableTiming);
        cudaEventCreateWithFlags(&ev1, cudaEventDisableTiming);
        cudaEventCreateWithFlags(&ev2, cudaEventDisableTiming);
        cudaEventCreateWithFlags(&ev3, cudaEventDisableTiming);
        cudaEventCreateWithFlags(&ev4, cudaEventDisableTiming);
        cudaFuncSetAttribute(k_gemmT, cudaFuncAttributeMaxDynamicSharedMemorySize, GEMM_SMEM);
    }
};

extern "C" void kernel_launch(void* const* d_in, const int* in_sizes, int n_in,
                              void* d_out, int out_size)
{
    static HxCtx ctx;

    const float* x    = (const float*)d_in[0];
    const void*  ei   = d_in[1];
    const void*  bi   = d_in[2];
    const float* mol  = (const float*)d_in[3];
    const float* gcnW = (const float*)d_in[4];
    const float* gcnB = (const float*)d_in[5];
    const float* goW  = (const float*)d_in[6];
    const float* goB  = (const float*)d_in[7];
    const float* mW   = (const float*)d_in[8];
    const float* mB   = (const float*)d_in[9];
    const float* moW  = (const float*)d_in[10];
    const float* moB  = (const float*)d_in[11];
    const float* p1W  = (const float*)d_in[12];
    const float* p1B  = (const float*)d_in[13];
    const float* p2W  = (const float*)d_in[14];
    const float* p2B  = (const float*)d_in[15];
    const float* oW   = (const float*)d_in[16];
    const float* oB   = (const float*)d_in[17];
    float* out = (float*)d_out;

    void *pT, *pX, *pW;
    cudaGetSymbolAddress(&pT, d_hT);
    cudaGetSymbolAddress(&pX, d_hX);
    cudaGetSymbolAddress(&pW, d_Wh);
    __half* hT = (__half*)pT;
    __half* hX = (__half*)pX;
    __half* Wh = (__half*)pW;

    const int nthr = 256;
    int gN = (NN + nthr - 1) / nthr;
    int gE = (NE + nthr - 1) / nthr;
    int gGemm = (NN + 127) / 128;
    int gAgg = (NN * 32 + nthr - 1) / nthr;

    cudaStream_t L = 0;

    // idx0: init (+is64 detect, scan flag reset)
    k_init<<<gN, nthr, 0, L>>>(ei);
    cudaEventRecord(ctx.ev0, L);
    cudaStreamWaitEvent(ctx.s1, ctx.ev0, 0);
    cudaStreamWaitEvent(ctx.s2, ctx.ev0, 0);

    // s1: CSR prep — idx1 hist, idx2 scan, idx3 fill (ncu target)
    k_hist<<<gE, nthr, 0, ctx.s1>>>(ei);
    k_scan<<<SCAN_NBLK, SCAN_BLK, 0, ctx.s1>>>();
    cudaEventRecord(ctx.ev4, ctx.s1);            // dinv ready
    k_fill<<<gE, nthr, 0, ctx.s1>>>(ei);
    cudaEventRecord(ctx.ev1, ctx.s1);            // CSR ready

    // s2: idx4 wconv, idx5 bounds, idx6 mlp
    k_wconv<<<(3 * NF * NF + 255) / 256, 256, 0, ctx.s2>>>(gcnW);
    cudaEventRecord(ctx.ev3, ctx.s2);
    k_bounds<<<gN, nthr, 0, ctx.s2>>>(bi);
    k_mlp<<<NG, nthr, 0, ctx.s2>>>(mol, mW, mB, moW, moB);
    cudaEventRecord(ctx.ev2, ctx.s2);

    // L: GCN stack (GEMM1 needs dinv for epilogue scaling + Wh)
    cudaStreamWaitEvent(L, ctx.ev3, 0);
    cudaStreamWaitEvent(L, ctx.ev4, 0);
    k_gemmT<<<gGemm, 256, GEMM_SMEM, L>>>(x, 1, Wh, hT, NN);
    cudaStreamWaitEvent(L, ctx.ev1, 0);
    k_agg<<<gAgg, 256, 0, L>>>(hT, gcnB, hX);
    k_gemmT<<<gGemm, 256, GEMM_SMEM, L>>>(hX, 0, Wh + NF * NF, hT, NN);
    k_agg<<<gAgg, 256, 0, L>>>(hT, gcnB + 128, hX);
    k_gemmT<<<gGemm, 256, GEMM_SMEM, L>>>(hX, 0, Wh + 2 * NF * NF, hT, NN);
    k_agg<<<gAgg, 256, 0, L>>>(hT, gcnB + 256, hX);

    cudaStreamWaitEvent(L, ctx.ev2, 0);
    k_heads2<<<NG, 256, 0, L>>>(hX, goW, goB, p1W, p1B, p2W, p2B, oW, oB, out);
}